// round 3
// baseline (speedup 1.0000x reference)
#include <cuda_runtime.h>
#include <cstddef>

#define DD      512
#define HWV     1024
#define NTOK    16384
#define NBLK    296            // 148 SMs x 2 CTAs -> perfect single wave
#define TPB     512
#define TOKTILE 16
#define NTILES  1024           // NTOK / TOKTILE

// scratch (no allocation allowed)
__device__ float  g_part[4][DD * NBLK];   // [q][blk*512 + d]  (coalesced writes)
__device__ float  g_br[NBLK];
__device__ double g_cd[DD];

// ---------------------------------------------------------------------------
// Pass 1: single sweep. Thread t -> dg = t&127 (d = 4dg..4dg+3), sub = t>>7
// (token subset). x staged via XOR-swizzled SMEM (conflict-free STS scalar
// transpose + conflict-free LDS.128). mu/lv read as float4, front-loaded.
// ---------------------------------------------------------------------------
__global__ __launch_bounds__(TPB, 2)
void club_pass1(const float* __restrict__ x,
                const float* __restrict__ mu,
                const float* __restrict__ lv)
{
    __shared__ float sx[TOKTILE * DD];     // 32 KB, swizzled [r][pg][k]
    const int tid = threadIdx.x;
    const int blk = blockIdx.x;
    const int dg  = tid & 127;             // d-group (4 consecutive d)
    const int sub = tid >> 7;              // token subset 0..3

    float a_sinv[4] = {0,0,0,0};
    float a_smui[4] = {0,0,0,0};
    float a_s1[4]   = {0,0,0,0};
    float a_s2[4]   = {0,0,0,0};
    float a_br = 0.f;

    // phase-A addressing: flat = rep*TPB + tid; d = flat>>2; v4 = flat&3
    const int dA  = tid >> 2;              // d for rep 0 (others add 128)
    const int v4A = tid & 3;
    const int gA  = dA >> 2, kA = dA & 3;
    const int r0  = v4A * 4;
    const int sw0 = (r0 + 0) * DD + kA + 4 * (((r0 + 0) >> 1) & 7) * 0; // placeholder unused

    for (int tile = blk; tile < NTILES; tile += NBLK) {
        const int b  = tile >> 6;                 // 64 tiles per batch
        const int s0 = (tile & 63) * TOKTILE;
        const int t0 = tile * TOKTILE;

        // ---- Phase A: load x tile [512 d x 16 tok], swizzled transpose ----
        const float* xb = x + (size_t)b * DD * HWV + s0 + (size_t)v4A * 4;
        const float4 xa0 = *reinterpret_cast<const float4*>(xb + (size_t)(dA +   0) * HWV);
        const float4 xa1 = *reinterpret_cast<const float4*>(xb + (size_t)(dA + 128) * HWV);
        const float4 xa2 = *reinterpret_cast<const float4*>(xb + (size_t)(dA + 256) * HWV);
        const float4 xa3 = *reinterpret_cast<const float4*>(xb + (size_t)(dA + 384) * HWV);

        #pragma unroll
        for (int rep = 0; rep < 4; rep++) {
            const float4 v = (rep == 0) ? xa0 : (rep == 1) ? xa1 : (rep == 2) ? xa2 : xa3;
            const int g = gA + rep * 32;          // (dA + rep*128) >> 2
            sx[(r0+0)*DD + 4*(g ^ (((r0+0)>>1)&7)) + kA] = v.x;
            sx[(r0+1)*DD + 4*(g ^ (((r0+1)>>1)&7)) + kA] = v.y;
            sx[(r0+2)*DD + 4*(g ^ (((r0+2)>>1)&7)) + kA] = v.z;
            sx[(r0+3)*DD + 4*(g ^ (((r0+3)>>1)&7)) + kA] = v.w;
        }
        __syncthreads();

        // ---- Phase B: mu/lv float4, front-loaded; x from swizzled SMEM ----
        const float* mup = mu + (size_t)(t0 + sub * 4) * DD + 4 * dg;
        const float* lvp = lv + (size_t)(t0 + sub * 4) * DD + 4 * dg;
        float4 m0 = *reinterpret_cast<const float4*>(mup + 0 * DD);
        float4 m1 = *reinterpret_cast<const float4*>(mup + 1 * DD);
        float4 m2 = *reinterpret_cast<const float4*>(mup + 2 * DD);
        float4 m3 = *reinterpret_cast<const float4*>(mup + 3 * DD);
        float4 l0 = *reinterpret_cast<const float4*>(lvp + 0 * DD);
        float4 l1 = *reinterpret_cast<const float4*>(lvp + 1 * DD);
        float4 l2 = *reinterpret_cast<const float4*>(lvp + 2 * DD);
        float4 l3 = *reinterpret_cast<const float4*>(lvp + 3 * DD);

        #pragma unroll
        for (int j = 0; j < 4; j++) {
            const int ts = sub * 4 + j;
            const float4 xv = *reinterpret_cast<const float4*>(
                &sx[ts * DD + 4 * (dg ^ ((ts >> 1) & 7))]);
            const float4 mm4 = (j == 0) ? m0 : (j == 1) ? m1 : (j == 2) ? m2 : m3;
            const float4 ll4 = (j == 0) ? l0 : (j == 1) ? l1 : (j == 2) ? l2 : l3;
            float mm[4] = {mm4.x, mm4.y, mm4.z, mm4.w};
            float ll[4] = {ll4.x, ll4.y, ll4.z, ll4.w};
            float xx[4] = {xv.x, xv.y, xv.z, xv.w};
            #pragma unroll
            for (int k = 0; k < 4; k++) {
                float iv = __expf(-ll[k]);
                a_sinv[k] += iv;
                a_smui[k] += mm[k] * iv;
                a_s1[k]   += xx[k];
                a_s2[k]   += xx[k] * xx[k];
                a_br      += (xx[k] - 2.0f * mm[k]) * xx[k] * iv;
            }
        }
        __syncthreads();
    }

    // ---- cross-sub combine via SMEM, then coalesced global write ----
    #pragma unroll
    for (int k = 0; k < 4; k++) {
        int base = (sub * 128 + dg) * 16 + k * 4;
        sx[base + 0] = a_sinv[k];
        sx[base + 1] = a_smui[k];
        sx[base + 2] = a_s1[k];
        sx[base + 3] = a_s2[k];
    }
    __syncthreads();
    {
        const int d   = tid;           // 0..511
        const int dg2 = d >> 2, kk = d & 3;
        float s0v = 0.f, s1v = 0.f, s2v = 0.f, s3v = 0.f;
        #pragma unroll
        for (int sb = 0; sb < 4; sb++) {
            int base = (sb * 128 + dg2) * 16 + kk * 4;
            s0v += sx[base + 0];
            s1v += sx[base + 1];
            s2v += sx[base + 2];
            s3v += sx[base + 3];
        }
        g_part[0][(size_t)blk * DD + d] = s0v;
        g_part[1][(size_t)blk * DD + d] = s1v;
        g_part[2][(size_t)blk * DD + d] = s2v;
        g_part[3][(size_t)blk * DD + d] = s3v;
    }
    __syncthreads();
    sx[tid] = a_br;
    __syncthreads();
    #pragma unroll
    for (int off = 256; off > 0; off >>= 1) {
        if (tid < off) sx[tid] += sx[tid + off];
        __syncthreads();
    }
    if (tid == 0) g_br[blk] = sx[0];
}

// ---------------------------------------------------------------------------
// Pass 2: 8 blocks x 256 thr. Block handles 64 d's; 4 blk-subsets per d read
// coalesced rows of g_part, combine deterministically, emit per-d double term
//   c[d] = -m2*Sinv + 2*m1*Smuinv
// ---------------------------------------------------------------------------
__global__ void club_pass2()
{
    __shared__ float red[4][4][64];    // [blk-subset][q][d-local]
    const int t  = threadIdx.x;
    const int d0 = blockIdx.x * 64;
    const int dl = t & 63;
    const int sb = t >> 6;             // 0..3

    float s0 = 0.f, s1 = 0.f, s2 = 0.f, s3 = 0.f;
    for (int blk = sb; blk < NBLK; blk += 4) {
        size_t idx = (size_t)blk * DD + d0 + dl;   // coalesced in dl
        s0 += g_part[0][idx];
        s1 += g_part[1][idx];
        s2 += g_part[2][idx];
        s3 += g_part[3][idx];
    }
    red[sb][0][dl] = s0;
    red[sb][1][dl] = s1;
    red[sb][2][dl] = s2;
    red[sb][3][dl] = s3;
    __syncthreads();
    if (t < 64) {
        float sinv = 0.f, smui = 0.f, xs1 = 0.f, xs2 = 0.f;
        #pragma unroll
        for (int k = 0; k < 4; k++) {
            sinv += red[k][0][t];
            smui += red[k][1][t];
            xs1  += red[k][2][t];
            xs2  += red[k][3][t];
        }
        double m1 = (double)xs1 / (double)NTOK;
        double m2 = (double)xs2 / (double)NTOK;
        g_cd[d0 + t] = -(m2 * (double)sinv) + 2.0 * m1 * (double)smui;
    }
}

// ---------------------------------------------------------------------------
// Pass 3: final deterministic double tree-sum -> scalar.
// ---------------------------------------------------------------------------
__global__ void club_pass3(float* __restrict__ out)
{
    __shared__ double sd[512];
    const int t = threadIdx.x;
    double v = g_cd[t];
    if (t < NBLK) v += (double)g_br[t];
    sd[t] = v;
    __syncthreads();
    #pragma unroll
    for (int off = 256; off > 0; off >>= 1) {
        if (t < off) sd[t] += sd[t + off];
        __syncthreads();
    }
    if (t == 0) out[0] = (float)(-0.5 / (double)NTOK * sd[0]);
}

// ---------------------------------------------------------------------------
extern "C" void kernel_launch(void* const* d_in, const int* in_sizes, int n_in,
                              void* d_out, int out_size)
{
    (void)in_sizes; (void)n_in; (void)out_size;
    const float* x  = (const float*)d_in[0];
    const float* mu = (const float*)d_in[1];
    const float* lv = (const float*)d_in[2];
    float* out = (float*)d_out;

    club_pass1<<<NBLK, TPB>>>(x, mu, lv);
    club_pass2<<<8, 256>>>();
    club_pass3<<<1, 512>>>(out);
}

// round 4
// speedup vs baseline: 1.3796x; 1.3796x over previous
#include <cuda_runtime.h>
#include <cstddef>

#define DD      512
#define HWV     1024
#define NTOK    16384
#define NBLK    296            // 148 SMs x 2 CTAs -> one wave, 7 vs 6 tiles/SM
#define NBP     320            // padded block count for pass2 (rows >=296 stay 0)
#define TPB     512
#define TOKTILE 16
#define NTILES  1024           // NTOK / TOKTILE
#define TILEF   (TOKTILE * DD) // floats per smem buffer (8192)

// scratch (no allocation allowed; device globals are zero-initialized)
__device__ float4 g_part4[NBP * DD];   // [blk*512 + d] = {sinv, smui, s1, s2}
__device__ float  g_br[NBLK];
__device__ double g_cd[DD];

// ---------------------------------------------------------------------------
// Pass 1: single sweep, double-buffered smem x-transpose, ONE sync per tile.
// Thread t -> dg = t&127 (d = 4dg..4dg+3), sub = t>>7 (token subset).
// x: LDG.128 (coalesced) -> XOR-swizzled STS (conflict-free) -> LDS.128.
// mu/lv: coalesced float4 loads. L2 prefetch two tiles ahead.
// ---------------------------------------------------------------------------
__global__ __launch_bounds__(TPB, 2)
void club_pass1(const float* __restrict__ x,
                const float* __restrict__ mu,
                const float* __restrict__ lv)
{
    extern __shared__ float sx[];          // 2 buffers x 32 KB
    const int tid = threadIdx.x;
    const int blk = blockIdx.x;
    const int dg  = tid & 127;
    const int sub = tid >> 7;

    // phase-A addressing: flat = rep*TPB + tid; d = flat>>2; v4 = flat&3
    const int dA  = tid >> 2;
    const int v4A = tid & 3;
    const int gA  = dA >> 2, kA = dA & 3;
    const int r0  = v4A * 4;
    // swizzled store columns are rep-invariant except g offset:
    const int c0 = 4 * (((r0 + 0) >> 1) & 7) ^ 0; // xor applied on g below
    (void)c0;

    float a_sinv[4] = {0,0,0,0};
    float a_smui[4] = {0,0,0,0};
    float a_s1[4]   = {0,0,0,0};
    float a_s2[4]   = {0,0,0,0};
    float a_br = 0.f;

    // ---- prologue: fill buffer 0 with tile 'blk' ----
    {
        const int b  = blk >> 6;
        const int s0 = (blk & 63) * TOKTILE;
        const float* xb = x + (size_t)b * DD * HWV + s0 + (size_t)v4A * 4;
        const float4 xa0 = *reinterpret_cast<const float4*>(xb + (size_t)(dA +   0) * HWV);
        const float4 xa1 = *reinterpret_cast<const float4*>(xb + (size_t)(dA + 128) * HWV);
        const float4 xa2 = *reinterpret_cast<const float4*>(xb + (size_t)(dA + 256) * HWV);
        const float4 xa3 = *reinterpret_cast<const float4*>(xb + (size_t)(dA + 384) * HWV);
        #pragma unroll
        for (int rep = 0; rep < 4; rep++) {
            const float4 v = (rep == 0) ? xa0 : (rep == 1) ? xa1 : (rep == 2) ? xa2 : xa3;
            const int g = gA + rep * 32;
            sx[(r0+0)*DD + 4*(g ^ (((r0+0)>>1)&7)) + kA] = v.x;
            sx[(r0+1)*DD + 4*(g ^ (((r0+1)>>1)&7)) + kA] = v.y;
            sx[(r0+2)*DD + 4*(g ^ (((r0+2)>>1)&7)) + kA] = v.z;
            sx[(r0+3)*DD + 4*(g ^ (((r0+3)>>1)&7)) + kA] = v.w;
        }
    }
    __syncthreads();

    int p = 0;
    for (int t = blk; t < NTILES; t += NBLK) {
        const int nxt = t + NBLK;

        // ---- L2 prefetch two tiles ahead (one 128B line per thread) ----
        const int tp = t + 2 * NBLK;
        if (tp < NTILES) {
            const float* pf = x + (size_t)(tp >> 6) * DD * HWV
                                + (size_t)tid * HWV + (tp & 63) * TOKTILE;
            asm volatile("prefetch.global.L2 [%0];" :: "l"(pf));
        }

        // ---- load next x tile and stage into the other buffer ----
        if (nxt < NTILES) {
            const int b  = nxt >> 6;
            const int s0 = (nxt & 63) * TOKTILE;
            const float* xb = x + (size_t)b * DD * HWV + s0 + (size_t)v4A * 4;
            const float4 xa0 = *reinterpret_cast<const float4*>(xb + (size_t)(dA +   0) * HWV);
            const float4 xa1 = *reinterpret_cast<const float4*>(xb + (size_t)(dA + 128) * HWV);
            const float4 xa2 = *reinterpret_cast<const float4*>(xb + (size_t)(dA + 256) * HWV);
            const float4 xa3 = *reinterpret_cast<const float4*>(xb + (size_t)(dA + 384) * HWV);
            float* sb = sx + (p ^ 1) * TILEF;
            #pragma unroll
            for (int rep = 0; rep < 4; rep++) {
                const float4 v = (rep == 0) ? xa0 : (rep == 1) ? xa1 : (rep == 2) ? xa2 : xa3;
                const int g = gA + rep * 32;
                sb[(r0+0)*DD + 4*(g ^ (((r0+0)>>1)&7)) + kA] = v.x;
                sb[(r0+1)*DD + 4*(g ^ (((r0+1)>>1)&7)) + kA] = v.y;
                sb[(r0+2)*DD + 4*(g ^ (((r0+2)>>1)&7)) + kA] = v.z;
                sb[(r0+3)*DD + 4*(g ^ (((r0+3)>>1)&7)) + kA] = v.w;
            }
        }

        // ---- phase B on current buffer ----
        {
            const int t0 = t * TOKTILE;
            const float* mup = mu + (size_t)(t0 + sub * 4) * DD + 4 * dg;
            const float* lvp = lv + (size_t)(t0 + sub * 4) * DD + 4 * dg;
            const float4 m0 = *reinterpret_cast<const float4*>(mup + 0 * DD);
            const float4 m1 = *reinterpret_cast<const float4*>(mup + 1 * DD);
            const float4 m2 = *reinterpret_cast<const float4*>(mup + 2 * DD);
            const float4 m3 = *reinterpret_cast<const float4*>(mup + 3 * DD);
            const float4 l0 = *reinterpret_cast<const float4*>(lvp + 0 * DD);
            const float4 l1 = *reinterpret_cast<const float4*>(lvp + 1 * DD);
            const float4 l2 = *reinterpret_cast<const float4*>(lvp + 2 * DD);
            const float4 l3 = *reinterpret_cast<const float4*>(lvp + 3 * DD);
            const float* cb = sx + p * TILEF;
            #pragma unroll
            for (int j = 0; j < 4; j++) {
                const int ts = sub * 4 + j;
                const float4 xv = *reinterpret_cast<const float4*>(
                    &cb[ts * DD + 4 * (dg ^ ((ts >> 1) & 7))]);
                const float4 mm4 = (j == 0) ? m0 : (j == 1) ? m1 : (j == 2) ? m2 : m3;
                const float4 ll4 = (j == 0) ? l0 : (j == 1) ? l1 : (j == 2) ? l2 : l3;
                float mm[4] = {mm4.x, mm4.y, mm4.z, mm4.w};
                float ll[4] = {ll4.x, ll4.y, ll4.z, ll4.w};
                float xx[4] = {xv.x, xv.y, xv.z, xv.w};
                #pragma unroll
                for (int k = 0; k < 4; k++) {
                    float iv = __expf(-ll[k]);
                    a_sinv[k] += iv;
                    a_smui[k] += mm[k] * iv;
                    a_s1[k]   += xx[k];
                    a_s2[k]   += xx[k] * xx[k];
                    a_br      += (xx[k] - 2.0f * mm[k]) * xx[k] * iv;
                }
            }
        }
        __syncthreads();
        p ^= 1;
    }

    // ---- cross-sub combine via SMEM, then coalesced float4 global write ----
    #pragma unroll
    for (int k = 0; k < 4; k++) {
        int base = (sub * 128 + dg) * 16 + k * 4;
        sx[base + 0] = a_sinv[k];
        sx[base + 1] = a_smui[k];
        sx[base + 2] = a_s1[k];
        sx[base + 3] = a_s2[k];
    }
    __syncthreads();
    {
        const int d   = tid;
        const int dg2 = d >> 2, kk = d & 3;
        float4 acc = make_float4(0.f, 0.f, 0.f, 0.f);
        #pragma unroll
        for (int sb = 0; sb < 4; sb++) {
            int base = (sb * 128 + dg2) * 16 + kk * 4;
            acc.x += sx[base + 0];
            acc.y += sx[base + 1];
            acc.z += sx[base + 2];
            acc.w += sx[base + 3];
        }
        g_part4[(size_t)blk * DD + d] = acc;   // coalesced STG.128
    }
    __syncthreads();
    sx[tid] = a_br;
    __syncthreads();
    #pragma unroll
    for (int off = 256; off > 0; off >>= 1) {
        if (tid < off) sx[tid] += sx[tid + off];
        __syncthreads();
    }
    if (tid == 0) g_br[blk] = sx[0];
}

// ---------------------------------------------------------------------------
// Pass 2: 32 blocks x 512 thr = 512 warps; warp <-> d, lane <-> blk chunk.
// 10 unrolled float4 loads per lane (padded rows are zero), shfl-xor butterfly,
// emit per-d double term c[d] = -m2*Sinv + 2*m1*Smuinv.
// ---------------------------------------------------------------------------
__global__ void club_pass2()
{
    const int w    = threadIdx.x >> 5;               // 0..15
    const int lane = threadIdx.x & 31;
    const int d    = blockIdx.x * 16 + w;            // 0..511

    float4 acc = make_float4(0.f, 0.f, 0.f, 0.f);
    #pragma unroll
    for (int k = 0; k < NBP / 32; k++) {
        float4 v = g_part4[(size_t)(k * 32 + lane) * DD + d];
        acc.x += v.x; acc.y += v.y; acc.z += v.z; acc.w += v.w;
    }
    #pragma unroll
    for (int off = 16; off > 0; off >>= 1) {
        acc.x += __shfl_xor_sync(0xFFFFFFFFu, acc.x, off);
        acc.y += __shfl_xor_sync(0xFFFFFFFFu, acc.y, off);
        acc.z += __shfl_xor_sync(0xFFFFFFFFu, acc.z, off);
        acc.w += __shfl_xor_sync(0xFFFFFFFFu, acc.w, off);
    }
    if (lane == 0) {
        double m1 = (double)acc.z / (double)NTOK;
        double m2 = (double)acc.w / (double)NTOK;
        g_cd[d] = -(m2 * (double)acc.x) + 2.0 * m1 * (double)acc.y;
    }
}

// ---------------------------------------------------------------------------
// Pass 3: final deterministic double tree-sum -> scalar.
// ---------------------------------------------------------------------------
__global__ void club_pass3(float* __restrict__ out)
{
    __shared__ double sd[512];
    const int t = threadIdx.x;
    double v = g_cd[t];
    if (t < NBLK) v += (double)g_br[t];
    sd[t] = v;
    __syncthreads();
    #pragma unroll
    for (int off = 256; off > 0; off >>= 1) {
        if (t < off) sd[t] += sd[t + off];
        __syncthreads();
    }
    if (t == 0) out[0] = (float)(-0.5 / (double)NTOK * sd[0]);
}

// ---------------------------------------------------------------------------
extern "C" void kernel_launch(void* const* d_in, const int* in_sizes, int n_in,
                              void* d_out, int out_size)
{
    (void)in_sizes; (void)n_in; (void)out_size;
    const float* x  = (const float*)d_in[0];
    const float* mu = (const float*)d_in[1];
    const float* lv = (const float*)d_in[2];
    float* out = (float*)d_out;

    const int smem = 2 * TILEF * (int)sizeof(float);   // 64 KB
    cudaFuncSetAttribute(club_pass1, cudaFuncAttributeMaxDynamicSharedMemorySize, smem);

    club_pass1<<<NBLK, TPB, smem>>>(x, mu, lv);
    club_pass2<<<32, 512>>>();
    club_pass3<<<1, 512>>>(out);
}